// round 1
// baseline (speedup 1.0000x reference)
#include <cuda_runtime.h>
#include <cuda_bf16.h>
#include <cstdint>

// Problem shapes (fixed for this dataset entry)
#define NC   4096      // coarse points
#define NS   16384     // fine (skip) points
#define CCH  256       // coarse feature channels
#define CS   128       // skip feature channels
#define DIN  384       // CCH + CS
#define HID  256       // hidden width

// Scratch (static device globals: allocation-free rule)
__device__ float g_ycat[(size_t)NS * DIN];   // [Ns, 384] concat(y, x_skip)
__device__ float g_h[(size_t)NS * HID];      // [Ns, 256] hidden activations

// ---------------------------------------------------------------------------
// Kernel 1: batch-segmented KNN (K=3) + inverse-d2 interpolation + skip concat
// 128 threads / block, 128 fine points / block.
// ---------------------------------------------------------------------------
__global__ __launch_bounds__(128)
void knn_interp_kernel(const float* __restrict__ x,
                       const float* __restrict__ pos,
                       const int*   __restrict__ batch,
                       const float* __restrict__ x_skip,
                       const float* __restrict__ pos_skip,
                       const int*   __restrict__ batch_skip,
                       float* __restrict__ ycat)
{
    __shared__ int   sIdx[128][3];
    __shared__ float sW[128][3];

    const int tid = threadIdx.x;
    const int gi  = blockIdx.x * 128 + tid;

    // ---- phase 1: per-thread top-3 scan over own batch segment ----
    const float px = pos_skip[3 * gi + 0];
    const float py = pos_skip[3 * gi + 1];
    const float pz = pos_skip[3 * gi + 2];
    const int   mb = batch_skip[gi];

    // lower_bound(batch, mb)
    int lo = 0, hi = NC;
    while (lo < hi) { int m = (lo + hi) >> 1; if (batch[m] < mb) lo = m + 1; else hi = m; }
    const int segs = lo;
    // upper_bound(batch, mb)
    lo = segs; hi = NC;
    while (lo < hi) { int m = (lo + hi) >> 1; if (batch[m] <= mb) lo = m + 1; else hi = m; }
    const int sege = lo;

    float d0 = 3e38f, d1 = 3e38f, d2 = 3e38f;
    int   i0 = 0,     i1 = 0,     i2 = 0;

    for (int j = segs; j < sege; ++j) {
        float dx = pos[3 * j + 0] - px;
        float dy = pos[3 * j + 1] - py;
        float dz = pos[3 * j + 2] - pz;
        float d  = fmaf(dx, dx, fmaf(dy, dy, dz * dz));
        if (d < d2) {
            if (d < d1) {
                d2 = d1; i2 = i1;
                if (d < d0) { d1 = d0; i1 = i0; d0 = d; i0 = j; }
                else        { d1 = d;  i1 = j; }
            } else { d2 = d; i2 = j; }
        }
    }

    float w0 = 1.0f / fmaxf(d0, 1e-16f);
    float w1 = 1.0f / fmaxf(d1, 1e-16f);
    float w2 = 1.0f / fmaxf(d2, 1e-16f);
    float inv_sw = 1.0f / (w0 + w1 + w2);

    sIdx[tid][0] = i0; sIdx[tid][1] = i1; sIdx[tid][2] = i2;
    sW[tid][0] = w0 * inv_sw; sW[tid][1] = w1 * inv_sw; sW[tid][2] = w2 * inv_sw;
    __syncthreads();

    // ---- phase 2: warp-cooperative gather-weighted-sum + skip concat ----
    const int warp = tid >> 5;
    const int lane = tid & 31;

    for (int r = warp; r < 128; r += 4) {
        const int g  = blockIdx.x * 128 + r;
        const int j0 = sIdx[r][0], j1 = sIdx[r][1], j2 = sIdx[r][2];
        const float a = sW[r][0], b = sW[r][1], c = sW[r][2];

        const float4* X0 = (const float4*)(x + (size_t)j0 * CCH);
        const float4* X1 = (const float4*)(x + (size_t)j1 * CCH);
        const float4* X2 = (const float4*)(x + (size_t)j2 * CCH);
        float4* Y = (float4*)(ycat + (size_t)g * DIN);

        #pragma unroll
        for (int v = lane; v < CCH / 4; v += 32) {
            float4 A = X0[v], B = X1[v], Cv = X2[v];
            float4 o;
            o.x = fmaf(a, A.x, fmaf(b, B.x, c * Cv.x));
            o.y = fmaf(a, A.y, fmaf(b, B.y, c * Cv.y));
            o.z = fmaf(a, A.z, fmaf(b, B.z, c * Cv.z));
            o.w = fmaf(a, A.w, fmaf(b, B.w, c * Cv.w));
            Y[v] = o;
        }
        // skip features: 128 floats = 32 float4 -> one per lane
        float4 sv = ((const float4*)(x_skip + (size_t)g * CS))[lane];
        ((float4*)(ycat + (size_t)g * DIN + CCH))[lane] = sv;
    }
}

// ---------------------------------------------------------------------------
// Kernel 2/3: SGEMM + bias + ReLU. C[M,N] = relu(A[M,K] @ B[K,N] + bias)
// BM=128, BN=128, BK=16, TM=TN=8, 256 threads. All dims divide tiles exactly.
// ---------------------------------------------------------------------------
__global__ __launch_bounds__(256)
void sgemm_bias_relu(int M, int N, int K,
                     const float* __restrict__ A,
                     const float* __restrict__ B,
                     const float* __restrict__ bias,
                     float* __restrict__ C)
{
    constexpr int BM = 128, BN = 128, BK = 16, TM = 8, TN = 8;
    __shared__ float As[BK][BM];
    __shared__ float Bs[BK][BN];

    const int tid = threadIdx.x;
    const int bc  = blockIdx.x;   // N tile
    const int br  = blockIdx.y;   // M tile

    const float* Ab = A + (size_t)br * BM * K;
    const float* Bb = B + (size_t)bc * BN;
    float* Cb = C + (size_t)br * BM * N + (size_t)bc * BN;

    // A tile loads: [BM][BK], 4 float4 per row; 256 threads -> 64 rows/pass, 2 passes
    const int aRow = tid >> 2;          // 0..63
    const int aCol = (tid & 3) * 4;     // 0,4,8,12
    // B tile loads: [BK][BN], 32 float4 per row; 8 rows/pass, 2 passes
    const int bRow = tid >> 5;          // 0..7
    const int bCol = (tid & 31) * 4;

    const int tRow = (tid >> 4) * TM;   // 0..120
    const int tCol = (tid & 15) * TN;   // 0..120

    float acc[TM][TN] = {};

    for (int k0 = 0; k0 < K; k0 += BK) {
        #pragma unroll
        for (int r = 0; r < BM; r += 64) {
            float4 v = *(const float4*)(Ab + (size_t)(aRow + r) * K + k0 + aCol);
            As[aCol + 0][aRow + r] = v.x;
            As[aCol + 1][aRow + r] = v.y;
            As[aCol + 2][aRow + r] = v.z;
            As[aCol + 3][aRow + r] = v.w;
        }
        #pragma unroll
        for (int r = 0; r < BK; r += 8) {
            *(float4*)(&Bs[bRow + r][bCol]) =
                *(const float4*)(Bb + (size_t)(bRow + r + k0) * N + bCol);
        }
        __syncthreads();

        #pragma unroll
        for (int k = 0; k < BK; ++k) {
            float4 a0 = *(const float4*)&As[k][tRow];
            float4 a1 = *(const float4*)&As[k][tRow + 4];
            float4 b0 = *(const float4*)&Bs[k][tCol];
            float4 b1 = *(const float4*)&Bs[k][tCol + 4];
            float ra[TM] = {a0.x, a0.y, a0.z, a0.w, a1.x, a1.y, a1.z, a1.w};
            float rb[TN] = {b0.x, b0.y, b0.z, b0.w, b1.x, b1.y, b1.z, b1.w};
            #pragma unroll
            for (int i = 0; i < TM; ++i)
                #pragma unroll
                for (int j = 0; j < TN; ++j)
                    acc[i][j] = fmaf(ra[i], rb[j], acc[i][j]);
        }
        __syncthreads();
    }

    float rbias[TN];
    #pragma unroll
    for (int j = 0; j < TN; ++j) rbias[j] = bias[(size_t)bc * BN + tCol + j];

    #pragma unroll
    for (int i = 0; i < TM; ++i) {
        #pragma unroll
        for (int j = 0; j < TN; j += 4) {
            float4 v;
            v.x = fmaxf(acc[i][j + 0] + rbias[j + 0], 0.0f);
            v.y = fmaxf(acc[i][j + 1] + rbias[j + 1], 0.0f);
            v.z = fmaxf(acc[i][j + 2] + rbias[j + 2], 0.0f);
            v.w = fmaxf(acc[i][j + 3] + rbias[j + 3], 0.0f);
            *(float4*)(Cb + (size_t)(tRow + i) * N + tCol + j) = v;
        }
    }
}

// ---------------------------------------------------------------------------
// Kernel 4: tail outputs — pos_skip copy + batch_skip->float, guarded by size
// ---------------------------------------------------------------------------
__global__ void tail_kernel(const float* __restrict__ pos_skip,
                            const int*   __restrict__ batch_skip,
                            float* __restrict__ out, int out_size)
{
    const int i = blockIdx.x * blockDim.x + threadIdx.x;
    const int base = NS * HID;
    if (i < NS * 3 && base + i < out_size)
        out[base + i] = pos_skip[i];
    if (i < NS && base + NS * 3 + i < out_size)
        out[base + NS * 3 + i] = (float)batch_skip[i];
}

// ---------------------------------------------------------------------------
extern "C" void kernel_launch(void* const* d_in, const int* in_sizes, int n_in,
                              void* d_out, int out_size)
{
    const float* x          = (const float*)d_in[0];
    const float* pos        = (const float*)d_in[1];
    const int*   batch      = (const int*)  d_in[2];
    const float* x_skip     = (const float*)d_in[3];
    const float* pos_skip   = (const float*)d_in[4];
    const int*   batch_skip = (const int*)  d_in[5];
    const float* W1         = (const float*)d_in[6];
    const float* b1         = (const float*)d_in[7];
    const float* W2         = (const float*)d_in[8];
    const float* b2         = (const float*)d_in[9];
    float* out = (float*)d_out;

    float* ycat; cudaGetSymbolAddress((void**)&ycat, g_ycat);
    float* h;    cudaGetSymbolAddress((void**)&h,    g_h);

    // 1) KNN + interpolate + concat
    knn_interp_kernel<<<NS / 128, 128>>>(x, pos, batch, x_skip, pos_skip, batch_skip, ycat);

    // 2) h = relu(ycat @ W1 + b1)   [16384 x 384] @ [384 x 256]
    {
        dim3 grid(HID / 128, NS / 128);
        sgemm_bias_relu<<<grid, 256>>>(NS, HID, DIN, ycat, W1, b1, h);
    }
    // 3) out = relu(h @ W2 + b2)    [16384 x 256] @ [256 x 256]
    {
        dim3 grid(HID / 128, NS / 128);
        sgemm_bias_relu<<<grid, 256>>>(NS, HID, HID, h, W2, b2, out);
    }
    // 4) tail outputs (pos_skip, batch_skip) if the flattened tuple is expected
    if (out_size > NS * HID) {
        int n = NS * 3;
        tail_kernel<<<(n + 255) / 256, 256>>>(pos_skip, batch_skip, out, out_size);
    }
}